// round 8
// baseline (speedup 1.0000x reference)
#include <cuda_runtime.h>
#include <cuda_fp16.h>
#include <cuda_bf16.h>
#include <stdint.h>

// Problem constants
#define BB   128
#define TT   1024
#define EE   256
#define HH   512
#define KK   768            // E + H
#define ROWG 16             // rows per rowgroup
#define NRG  8              // rowgroups
#define NSPL 16             // gate-split blocks per rowgroup
#define PITCH  776          // smem row pitch in halfs (1552B, 1552%128=16 -> conflict-free ldmatrix)
#define GPITCH 132          // gate smem pitch (floats)
#define OFF_A  (128 * PITCH * 2)                // 198656 bytes: weights region
#define SMEM_BYTES (OFF_A + ROWG * PITCH * 2)   // 223488 bytes total

// Persistent device scratch (static globals are allowed; no allocation)
__device__ __half   g_hbuf[2][BB][HH];   // double-buffered recurrent h (fp16)
__device__ float    g_lastH[BB][HH];
__device__ float    g_lastC[BB][HH];
__device__ int      g_sentLen[BB];
__device__ unsigned g_ctr[NRG];          // per-rowgroup monotonic barrier counters

// ---------------------------------------------------------------------------
__device__ __forceinline__ uint32_t smem_u32(const void* p) {
    return (uint32_t)__cvta_generic_to_shared(p);
}
__device__ __forceinline__ void ldsm_x4(uint32_t& r0, uint32_t& r1, uint32_t& r2, uint32_t& r3, uint32_t a) {
    asm volatile("ldmatrix.sync.aligned.m8n8.x4.shared.b16 {%0,%1,%2,%3}, [%4];\n"
                 : "=r"(r0), "=r"(r1), "=r"(r2), "=r"(r3) : "r"(a));
}
__device__ __forceinline__ void ldsm_x2(uint32_t& r0, uint32_t& r1, uint32_t a) {
    asm volatile("ldmatrix.sync.aligned.m8n8.x2.shared.b16 {%0,%1}, [%2];\n"
                 : "=r"(r0), "=r"(r1) : "r"(a));
}
__device__ __forceinline__ void mma16816(float* d, uint32_t a0, uint32_t a1, uint32_t a2, uint32_t a3,
                                         uint32_t b0, uint32_t b1) {
    asm volatile("mma.sync.aligned.m16n8k16.row.col.f32.f16.f16.f32 "
                 "{%0,%1,%2,%3}, {%4,%5,%6,%7}, {%8,%9}, {%0,%1,%2,%3};\n"
                 : "+f"(d[0]), "+f"(d[1]), "+f"(d[2]), "+f"(d[3])
                 : "r"(a0), "r"(a1), "r"(a2), "r"(a3), "r"(b0), "r"(b1));
}
__device__ __forceinline__ float sigf(float x)     { return 1.0f / (1.0f + __expf(-x)); }
__device__ __forceinline__ float tanhfast(float x) { return 2.0f / (1.0f + __expf(-2.0f * x)) - 1.0f; }

// ---------------------------------------------------------------------------
// Kernel 0: sent_len per row (index of first zero token, minus one) + reset barriers
__global__ void prep_kernel(const int* __restrict__ tokens) {
    const int row = blockIdx.x;
    const int tid = threadIdx.x;   // 128 threads
    int first = TT;
    for (int t = tid; t < TT; t += 128)
        if (tokens[row * TT + t] == 0) first = min(first, t);
    __shared__ int s[4];
    #pragma unroll
    for (int o = 16; o; o >>= 1) first = min(first, __shfl_down_sync(0xffffffffu, first, o));
    if ((tid & 31) == 0) s[tid >> 5] = first;
    __syncthreads();
    if (tid == 0) {
        int f  = min(min(s[0], s[1]), min(s[2], s[3]));
        int sl = f - 1;
        if (sl < 0) sl += TT;        // python negative-index wrap (defensive)
        g_sentLen[row] = sl;
        if (row < NRG) g_ctr[row] = 0;
    }
}

// ---------------------------------------------------------------------------
// Kernel 1: persistent fused LSTM recurrence.
// grid = 128 blocks (8 rowgroups x 16 gate-slices), 256 threads, 1 CTA/SM.
__global__ void __launch_bounds__(256, 1)
lstm_kernel(const int* __restrict__ tokens, const float* __restrict__ emb,
            const float* __restrict__ W_ih, const float* __restrict__ b_ih,
            const float* __restrict__ W_hh, const float* __restrict__ b_hh,
            const float* __restrict__ h0,   const float* __restrict__ c0)
{
    extern __shared__ unsigned char smem[];
    __half* sW = (__half*)smem;               // [128][PITCH] fp16 weight slice (persistent)
    __half* sA = (__half*)(smem + OFF_A);     // [16][PITCH]  fp16 activations [x_t | h]
    float*  sG = (float*)(smem + OFF_A);      // [2][16][GPITCH] gate partials (aliased over sA)

    const int tid  = threadIdx.x;
    const int rg   = blockIdx.x >> 4;         // rowgroup
    const int ns   = blockIdx.x & 15;         // gate-slice (32 hidden units)
    const int row0 = rg * ROWG;

    // ---- load weight slice to SMEM (fp16). local gate row r -> global row
    //      gr = gate*512 + ns*32 + unit, cols = [W_ih | W_hh]
    for (int idx = tid; idx < 128 * KK; idx += 256) {
        const int r  = idx / KK;
        const int k  = idx - r * KK;
        const int gr = ((r >> 5) << 9) + (ns << 5) + (r & 31);
        const float v = (k < EE) ? W_ih[gr * EE + k] : W_hh[gr * HH + (k - EE)];
        sW[r * PITCH + k] = __float2half_rn(v);
    }

    // ---- per-thread LSTM cell state: two (row, unit) pairs per thread
    const int idxA = tid * 2, idxB = tid * 2 + 1;
    const int rA = idxA >> 5, uA = idxA & 31;
    const int rB = idxB >> 5, uB = idxB & 31;
    const int colA = (ns << 5) + uA, colB = (ns << 5) + uB;
    const int growA = row0 + rA, growB = row0 + rB;
    const float biA = b_ih[colA]        + b_hh[colA];
    const float bfA = b_ih[512 + colA]  + b_hh[512 + colA];
    const float bgA = b_ih[1024 + colA] + b_hh[1024 + colA];
    const float boA = b_ih[1536 + colA] + b_hh[1536 + colA];
    const float biB = b_ih[colB]        + b_hh[colB];
    const float bfB = b_ih[512 + colB]  + b_hh[512 + colB];
    const float bgB = b_ih[1024 + colB] + b_hh[1024 + colB];
    const float boB = b_ih[1536 + colB] + b_hh[1536 + colB];
    float cA = c0[growA * HH + colA];
    float cB = c0[growB * HH + colB];
    const int slA = g_sentLen[growA];
    const int slB = g_sentLen[growB];

    int tmax = 1;
    #pragma unroll
    for (int r = 0; r < ROWG; ++r) tmax = max(tmax, g_sentLen[row0 + r]);

    // ---- warp MMA geometry: warp = (k-half, n-tile of 32 gate cols)
    const int lane = tid & 31, wid = tid >> 5;
    const int kh = wid >> 2;                  // 0/1 -> K [0,384) / [384,768)
    const int nt = wid & 3;                   // n0 = nt*32
    const int kbyte = kh * 384 * 2;

    const int a_row = lane & 15;              // lanes 0-15 rows 0-15, 16-31 repeat
    const uint32_t aBase = smem_u32(sA) + a_row * (PITCH * 2) + ((lane >> 4) & 1) * 16 + kbyte;
    uint32_t bBase[4];
    const int b_lrow = lane & 7;
    const int b_csel = (lane >> 3) & 1;
    #pragma unroll
    for (int j = 0; j < 4; ++j)
        bBase[j] = smem_u32(sW) + (nt * 32 + j * 8 + b_lrow) * (PITCH * 2) + b_csel * 16 + kbyte;

    const int gr_r = tid >> 4;                // loader mapping: row 0..15
    const int gr_c = tid & 15;                // chunk 0..15

    __syncthreads();                          // weights ready

    for (int t = 0; t <= tmax; ++t) {
        // ---- gather x_t -> sA[:, 0:256] (before barrier wait: latency hides in spin)
        {
            const int tok = tokens[(row0 + gr_r) * TT + t];
            const float4* src = (const float4*)(emb + (size_t)tok * EE + gr_c * 16);
            __half2* dst = (__half2*)(sA + gr_r * PITCH + gr_c * 16);
            #pragma unroll
            for (int q = 0; q < 4; ++q) {
                const float4 v = __ldg(src + q);
                dst[2 * q]     = __floats2half2_rn(v.x, v.y);
                dst[2 * q + 1] = __floats2half2_rn(v.z, v.w);
            }
        }
        // ---- h(t-1) -> sA[:, 256:768]
        if (t == 0) {
            const float4* src = (const float4*)(h0 + (row0 + gr_r) * HH + gr_c * 32);
            __half2* dst = (__half2*)(sA + gr_r * PITCH + EE + gr_c * 32);
            #pragma unroll
            for (int q = 0; q < 8; ++q) {
                const float4 v = __ldg(src + q);
                dst[2 * q]     = __floats2half2_rn(v.x, v.y);
                dst[2 * q + 1] = __floats2half2_rn(v.z, v.w);
            }
        } else {
            if (tid == 0) {
                const unsigned target = (unsigned)(NSPL * t);
                while (*((volatile unsigned*)&g_ctr[rg]) < target) { }
            }
            __syncthreads();
            __threadfence();   // acquire before reading peers' h
            const uint4* src = (const uint4*)(&g_hbuf[(t - 1) & 1][row0 + gr_r][gr_c * 32]);
            uint4* dst = (uint4*)(sA + gr_r * PITCH + EE + gr_c * 32);
            #pragma unroll
            for (int q = 0; q < 4; ++q) dst[q] = __ldcg(src + q);   // bypass stale L1
        }
        __syncthreads();

        // ---- MMA: m16 x n32 x k384 per warp (24 k-steps)
        float d[4][4];
        #pragma unroll
        for (int j = 0; j < 4; ++j) d[j][0] = d[j][1] = d[j][2] = d[j][3] = 0.0f;
        #pragma unroll 4
        for (int ks = 0; ks < 24; ++ks) {
            uint32_t a0, a1, a2, a3;
            ldsm_x4(a0, a1, a2, a3, aBase + ks * 32);
            #pragma unroll
            for (int j = 0; j < 4; ++j) {
                uint32_t b0, b1;
                ldsm_x2(b0, b1, bBase[j] + ks * 32);
                mma16816(d[j], a0, a1, a2, a3, b0, b1);
            }
        }
        __syncthreads();   // all MMA reads of sA done before sG (aliased) is written

        // ---- write gate partials to sG[kh]
        {
            const int gg = lane >> 2, tg = lane & 3;
            float* base = sG + (kh * 16 + gg) * GPITCH + nt * 32 + tg * 2;
            #pragma unroll
            for (int j = 0; j < 4; ++j) {
                float* p = base + j * 8;
                *(float2*)p                 = make_float2(d[j][0], d[j][1]);
                *(float2*)(p + 8 * GPITCH)  = make_float2(d[j][2], d[j][3]);
            }
        }
        __syncthreads();

        // ---- activations + cell update (sum the two k-halves)
        {
            const float* g0 = sG + rA * GPITCH;
            const float* g1 = sG + (16 + rA) * GPITCH;
            const float gi = g0[uA]      + g1[uA]      + biA;
            const float gf = g0[32 + uA] + g1[32 + uA] + bfA;
            const float gc = g0[64 + uA] + g1[64 + uA] + bgA;
            const float go = g0[96 + uA] + g1[96 + uA] + boA;
            cA = sigf(gf) * cA + sigf(gi) * tanhfast(gc);
            const float hv = sigf(go) * tanhfast(cA);
            g_hbuf[t & 1][growA][colA] = __float2half_rn(hv);
            if (t == slA) { g_lastH[growA][colA] = hv; g_lastC[growA][colA] = cA; }
        }
        {
            const float* g0 = sG + rB * GPITCH;
            const float* g1 = sG + (16 + rB) * GPITCH;
            const float gi = g0[uB]      + g1[uB]      + biB;
            const float gf = g0[32 + uB] + g1[32 + uB] + bfB;
            const float gc = g0[64 + uB] + g1[64 + uB] + bgB;
            const float go = g0[96 + uB] + g1[96 + uB] + boB;
            cB = sigf(gf) * cB + sigf(gi) * tanhfast(gc);
            const float hv = sigf(go) * tanhfast(cB);
            g_hbuf[t & 1][growB][colB] = __float2half_rn(hv);
            if (t == slB) { g_lastH[growB][colB] = hv; g_lastC[growB][colB] = cB; }
        }
        __threadfence();   // release h before arrive
        __syncthreads();
        if (tid == 0) atomicAdd(&g_ctr[rg], 1u);
    }
}

// ---------------------------------------------------------------------------
// Kernel 2: head. One block per batch row: y = last@W_proj^T + b_proj; out = y@W_out^T + b_out
__global__ void __launch_bounds__(256)
head_kernel(const float* __restrict__ W_proj, const float* __restrict__ b_proj,
            const float* __restrict__ W_out,  const float* __restrict__ b_out,
            float* __restrict__ out)
{
    __shared__ __align__(16) float last[2 * HH];
    __shared__ float y[HH];
    __shared__ float red[16];
    const int row = blockIdx.x, tid = threadIdx.x;

    for (int i = tid; i < HH; i += 256) {
        last[i]      = g_lastH[row][i];
        last[HH + i] = g_lastC[row][i];
    }
    __syncthreads();

    for (int j = tid; j < HH; j += 256) {
        const float4* w  = (const float4*)(W_proj + j * (2 * HH));
        const float4* l4 = (const float4*)last;
        float s = b_proj[j];
        #pragma unroll 8
        for (int k = 0; k < (2 * HH) / 4; ++k) {
            const float4 a = __ldg(w + k);
            const float4 b = l4[k];
            s += a.x * b.x + a.y * b.y + a.z * b.z + a.w * b.w;
        }
        y[j] = s;
    }
    __syncthreads();

    float s0 = 0.0f, s1 = 0.0f;
    for (int j = tid; j < HH; j += 256) {
        s0 += y[j] * W_out[j];
        s1 += y[j] * W_out[HH + j];
    }
    #pragma unroll
    for (int o = 16; o; o >>= 1) {
        s0 += __shfl_down_sync(0xffffffffu, s0, o);
        s1 += __shfl_down_sync(0xffffffffu, s1, o);
    }
    if ((tid & 31) == 0) { red[tid >> 5] = s0; red[8 + (tid >> 5)] = s1; }
    __syncthreads();
    if (tid == 0) {
        float a = b_out[0], b = b_out[1];
        #pragma unroll
        for (int w = 0; w < 8; ++w) { a += red[w]; b += red[8 + w]; }
        out[row * 2 + 0] = a;
        out[row * 2 + 1] = b;
    }
}

// ---------------------------------------------------------------------------
extern "C" void kernel_launch(void* const* d_in, const int* in_sizes, int n_in,
                              void* d_out, int out_size)
{
    (void)in_sizes; (void)n_in; (void)out_size;
    const int*   tokens = (const int*)  d_in[0];
    const float* emb    = (const float*)d_in[1];
    const float* W_ih   = (const float*)d_in[2];
    const float* b_ih   = (const float*)d_in[3];
    const float* W_hh   = (const float*)d_in[4];
    const float* b_hh   = (const float*)d_in[5];
    const float* W_proj = (const float*)d_in[6];
    const float* b_proj = (const float*)d_in[7];
    const float* W_out  = (const float*)d_in[8];
    const float* b_out  = (const float*)d_in[9];
    const float* h0     = (const float*)d_in[10];
    const float* c0     = (const float*)d_in[11];
    float* out = (float*)d_out;

    cudaFuncSetAttribute(lstm_kernel, cudaFuncAttributeMaxDynamicSharedMemorySize, SMEM_BYTES);

    prep_kernel<<<BB, 128>>>(tokens);
    lstm_kernel<<<NRG * NSPL, 256, SMEM_BYTES>>>(tokens, emb, W_ih, b_ih, W_hh, b_hh, h0, c0);
    head_kernel<<<BB, 256>>>(W_proj, b_proj, W_out, b_out, out);
}

// round 10
// speedup vs baseline: 1.0783x; 1.0783x over previous
#include <cuda_runtime.h>
#include <cuda_fp16.h>
#include <cuda_bf16.h>
#include <stdint.h>

// Problem constants
#define BB   128
#define TT   1024
#define EE   256
#define HH   512
#define KK   768
#define ROWG 16             // rows per rowgroup
#define NRG  8              // rowgroups
#define NSPL 16             // gate-split blocks per rowgroup
#define WPITCH 776          // weight smem pitch (halfs): 1552B, %128=16 -> conflict-free ldmatrix
#define XPITCH 264          // x buffer pitch (halfs): 528B, %128=16
#define HPITCH 520          // h buffer pitch (halfs): 1040B, %128=16
#define GPITCH 130          // gate partial pitch (floats)
#define OFF_X0 (128 * WPITCH * 2)               // 198656
#define OFF_X1 (OFF_X0 + ROWG * XPITCH * 2)     // 207104
#define OFF_H  (OFF_X1 + ROWG * XPITCH * 2)     // 215552
#define SMEM_BYTES (OFF_H + ROWG * HPITCH * 2)  // 232192 <= 232448 cap

// Persistent device scratch
__device__ __half   g_hbuf[2][BB][HH];   // double-buffered recurrent h (fp16)
__device__ float    g_lastH[BB][HH];
__device__ float    g_lastC[BB][HH];
__device__ int      g_sentLen[BB];
__device__ unsigned g_ctr[NRG];          // per-rowgroup monotonic barrier counters

// ---------------------------------------------------------------------------
__device__ __forceinline__ uint32_t smem_u32(const void* p) {
    return (uint32_t)__cvta_generic_to_shared(p);
}
__device__ __forceinline__ void ldsm_x4(uint32_t& r0, uint32_t& r1, uint32_t& r2, uint32_t& r3, uint32_t a) {
    asm volatile("ldmatrix.sync.aligned.m8n8.x4.shared.b16 {%0,%1,%2,%3}, [%4];\n"
                 : "=r"(r0), "=r"(r1), "=r"(r2), "=r"(r3) : "r"(a));
}
__device__ __forceinline__ void ldsm_x2(uint32_t& r0, uint32_t& r1, uint32_t a) {
    asm volatile("ldmatrix.sync.aligned.m8n8.x2.shared.b16 {%0,%1}, [%2];\n"
                 : "=r"(r0), "=r"(r1) : "r"(a));
}
__device__ __forceinline__ void mma16816(float* d, uint32_t a0, uint32_t a1, uint32_t a2, uint32_t a3,
                                         uint32_t b0, uint32_t b1) {
    asm volatile("mma.sync.aligned.m16n8k16.row.col.f32.f16.f16.f32 "
                 "{%0,%1,%2,%3}, {%4,%5,%6,%7}, {%8,%9}, {%0,%1,%2,%3};\n"
                 : "+f"(d[0]), "+f"(d[1]), "+f"(d[2]), "+f"(d[3])
                 : "r"(a0), "r"(a1), "r"(a2), "r"(a3), "r"(b0), "r"(b1));
}
__device__ __forceinline__ unsigned ld_acquire(const unsigned* p) {
    unsigned v;
    asm volatile("ld.global.acquire.gpu.b32 %0, [%1];\n" : "=r"(v) : "l"(p) : "memory");
    return v;
}
__device__ __forceinline__ float sigf(float x)     { return 1.0f / (1.0f + __expf(-x)); }
__device__ __forceinline__ float tanhfast(float x) { return 2.0f / (1.0f + __expf(-2.0f * x)) - 1.0f; }

// ---------------------------------------------------------------------------
// Kernel 0: sent_len per row + reset barriers
__global__ void prep_kernel(const int* __restrict__ tokens) {
    const int row = blockIdx.x;
    const int tid = threadIdx.x;   // 128 threads
    int first = TT;
    for (int t = tid; t < TT; t += 128)
        if (tokens[row * TT + t] == 0) first = min(first, t);
    __shared__ int s[4];
    #pragma unroll
    for (int o = 16; o; o >>= 1) first = min(first, __shfl_down_sync(0xffffffffu, first, o));
    if ((tid & 31) == 0) s[tid >> 5] = first;
    __syncthreads();
    if (tid == 0) {
        int f  = min(min(s[0], s[1]), min(s[2], s[3]));
        int sl = f - 1;
        if (sl < 0) sl += TT;        // python negative-index wrap (defensive)
        g_sentLen[row] = sl;
        if (row < NRG) g_ctr[row] = 0;
    }
}

// ---------------------------------------------------------------------------
// Kernel 1: persistent fused LSTM. grid = 128 blocks (8 rowgroups x 16 gate
// slices), 256 threads, 1 CTA/SM, all co-resident.
__global__ void __launch_bounds__(256, 1)
lstm_kernel(const int* __restrict__ tokens, const float* __restrict__ emb,
            const float* __restrict__ W_ih, const float* __restrict__ b_ih,
            const float* __restrict__ W_hh, const float* __restrict__ b_hh,
            const float* __restrict__ h0,   const float* __restrict__ c0)
{
    extern __shared__ unsigned char smem[];
    __half* sW  = (__half*)smem;                 // [128][WPITCH] weights (persistent)
    __half* sX0 = (__half*)(smem + OFF_X0);      // [16][XPITCH] x buffer 0
    __half* sX1 = (__half*)(smem + OFF_X1);      // [16][XPITCH] x buffer 1
    __half* sH  = (__half*)(smem + OFF_H);       // [16][HPITCH] h buffer
    float*  sG  = (float*)(smem + OFF_H);        // [2][16][GPITCH] gate partials (alias over sH)

    const int tid  = threadIdx.x;
    const int rg   = blockIdx.x >> 4;
    const int ns   = blockIdx.x & 15;
    const int row0 = rg * ROWG;

    // ---- weight slice -> SMEM fp16: local gate row r -> gr = gate*512 + ns*32 + unit
    for (int idx = tid; idx < 128 * KK; idx += 256) {
        const int r  = idx / KK;
        const int k  = idx - r * KK;
        const int gr = ((r >> 5) << 9) + (ns << 5) + (r & 31);
        const float v = (k < EE) ? W_ih[gr * EE + k] : W_hh[gr * HH + (k - EE)];
        sW[r * WPITCH + k] = __float2half_rn(v);
    }

    // ---- per-thread cell state (two (row, unit) pairs)
    const int idxA = tid * 2, idxB = tid * 2 + 1;
    const int rA = idxA >> 5, uA = idxA & 31;
    const int rB = idxB >> 5, uB = idxB & 31;
    const int colA = (ns << 5) + uA, colB = (ns << 5) + uB;
    const int growA = row0 + rA, growB = row0 + rB;
    const float biA = b_ih[colA]        + b_hh[colA];
    const float bfA = b_ih[512 + colA]  + b_hh[512 + colA];
    const float bgA = b_ih[1024 + colA] + b_hh[1024 + colA];
    const float boA = b_ih[1536 + colA] + b_hh[1536 + colA];
    const float biB = b_ih[colB]        + b_hh[colB];
    const float bfB = b_ih[512 + colB]  + b_hh[512 + colB];
    const float bgB = b_ih[1024 + colB] + b_hh[1024 + colB];
    const float boB = b_ih[1536 + colB] + b_hh[1536 + colB];
    float cA = c0[growA * HH + colA];
    float cB = c0[growB * HH + colB];
    const int slA = g_sentLen[growA];
    const int slB = g_sentLen[growB];

    int tmax = 1;
    #pragma unroll
    for (int r = 0; r < ROWG; ++r) tmax = max(tmax, g_sentLen[row0 + r]);

    // ---- warp MMA geometry: warp = (k-half, n-tile of 32 gate cols)
    const int lane = tid & 31, wid = tid >> 5;
    const int kh = wid >> 2;
    const int nt = wid & 3;

    const int a_row = lane & 15;
    const int asel  = ((lane >> 4) & 1) * 16;
    const uint32_t aX[2] = {
        smem_u32(sX0) + a_row * (XPITCH * 2) + asel + kh * 256,
        smem_u32(sX1) + a_row * (XPITCH * 2) + asel + kh * 256 };
    const uint32_t aH = smem_u32(sH) + a_row * (HPITCH * 2) + asel + kh * 512;

    uint32_t bX[4], bH[4];
    const int b_lrow = lane & 7;
    const int b_csel = ((lane >> 3) & 1) * 16;
    #pragma unroll
    for (int j = 0; j < 4; ++j) {
        const uint32_t base = smem_u32(sW) + (nt * 32 + j * 8 + b_lrow) * (WPITCH * 2) + b_csel;
        bX[j] = base + kh * 256;          // W_ih cols [0,256): kh*128 halfs
        bH[j] = base + 512 + kh * 512;    // W_hh cols [256,768): 256 + kh*256 halfs
    }

    const int gr_r = tid >> 4;            // loader row 0..15
    const int gr_c = tid & 15;            // loader chunk 0..15

    // ---- prologue: stage x(0) into buf0; prefetch token(1)
    {
        const int tok0 = tokens[(row0 + gr_r) * TT + 0];
        const float4* src = (const float4*)(emb + (size_t)tok0 * EE + gr_c * 16);
        __half2* dst = (__half2*)(sX0 + gr_r * XPITCH + gr_c * 16);
        #pragma unroll
        for (int q = 0; q < 4; ++q) {
            const float4 v = __ldg(src + q);
            dst[2 * q]     = __floats2half2_rn(v.x, v.y);
            dst[2 * q + 1] = __floats2half2_rn(v.z, v.w);
        }
    }
    int tok_next = tokens[(row0 + gr_r) * TT + 1];
    __syncthreads();                      // weights + x(0) ready

    for (int t = 0; t <= tmax; ++t) {
        // ---- P1: prefetch emb rows for x(t+1) into registers (full-step cover)
        float4 xv0, xv1, xv2, xv3;
        const bool doX = (t < tmax);
        if (doX) {
            const float4* src = (const float4*)(emb + (size_t)tok_next * EE + gr_c * 16);
            xv0 = __ldg(src + 0); xv1 = __ldg(src + 1);
            xv2 = __ldg(src + 2); xv3 = __ldg(src + 3);
        }
        const int tok_after = tokens[(row0 + gr_r) * TT + min(t + 2, TT - 1)];

        // ---- P2: x-GEMM (off the h critical path): m16 x n32 x k128 per warp
        float d[4][4];
        #pragma unroll
        for (int j = 0; j < 4; ++j) d[j][0] = d[j][1] = d[j][2] = d[j][3] = 0.0f;
        {
            const uint32_t aB = aX[t & 1];
            #pragma unroll
            for (int ks = 0; ks < 8; ++ks) {
                uint32_t a0, a1, a2, a3;
                ldsm_x4(a0, a1, a2, a3, aB + ks * 32);
                #pragma unroll
                for (int j = 0; j < 4; ++j) {
                    uint32_t b0, b1;
                    ldsm_x2(b0, b1, bX[j] + ks * 32);
                    mma16816(d[j], a0, a1, a2, a3, b0, b1);
                }
            }
        }

        // ---- P3: stage x(t+1) into the other buffer
        if (doX) {
            __half2* dst = (__half2*)(((t + 1) & 1 ? sX1 : sX0) + gr_r * XPITCH + gr_c * 16);
            dst[0] = __floats2half2_rn(xv0.x, xv0.y); dst[1] = __floats2half2_rn(xv0.z, xv0.w);
            dst[2] = __floats2half2_rn(xv1.x, xv1.y); dst[3] = __floats2half2_rn(xv1.z, xv1.w);
            dst[4] = __floats2half2_rn(xv2.x, xv2.y); dst[5] = __floats2half2_rn(xv2.z, xv2.w);
            dst[6] = __floats2half2_rn(xv3.x, xv3.y); dst[7] = __floats2half2_rn(xv3.z, xv3.w);
        }
        tok_next = tok_after;

        // ---- P4: barrier + load h(t-1) into sH (sG alias consumed last step)
        if (t == 0) {
            const float4* src = (const float4*)(h0 + (row0 + gr_r) * HH + gr_c * 32);
            __half2* dst = (__half2*)(sH + gr_r * HPITCH + gr_c * 32);
            #pragma unroll
            for (int q = 0; q < 8; ++q) {
                const float4 v = __ldg(src + q);
                dst[2 * q]     = __floats2half2_rn(v.x, v.y);
                dst[2 * q + 1] = __floats2half2_rn(v.z, v.w);
            }
        } else {
            if (tid == 0) {
                const unsigned target = 128u * (unsigned)t;   // 16 blocks x 8 warps per step
                while (ld_acquire(&g_ctr[rg]) < target) { }
            }
            __syncthreads();
            const uint4* src = (const uint4*)(&g_hbuf[(t - 1) & 1][row0 + gr_r][gr_c * 32]);
            uint4* dst = (uint4*)((unsigned char*)sH + gr_r * (HPITCH * 2) + gr_c * 64);
            #pragma unroll
            for (int q = 0; q < 4; ++q) dst[q] = __ldcg(src + q);   // L2-coherent
        }
        __syncthreads();

        // ---- P5: h-GEMM (critical path): m16 x n32 x k256 per warp
        #pragma unroll 4
        for (int ks = 0; ks < 16; ++ks) {
            uint32_t a0, a1, a2, a3;
            ldsm_x4(a0, a1, a2, a3, aH + ks * 32);
            #pragma unroll
            for (int j = 0; j < 4; ++j) {
                uint32_t b0, b1;
                ldsm_x2(b0, b1, bH[j] + ks * 32);
                mma16816(d[j], a0, a1, a2, a3, b0, b1);
            }
        }
        __syncthreads();   // all reads of sH done before sG (alias) written

        // ---- P6: gate partials -> sG[kh]
        {
            const int gg = lane >> 2, tg = lane & 3;
            float* base = sG + (kh * 16 + gg) * GPITCH + nt * 32 + tg * 2;
            #pragma unroll
            for (int j = 0; j < 4; ++j) {
                float* p = base + j * 8;
                *(float2*)p                 = make_float2(d[j][0], d[j][1]);
                *(float2*)(p + 8 * GPITCH)  = make_float2(d[j][2], d[j][3]);
            }
        }
        __syncthreads();

        // ---- P7: activations + cell update (sum two k-halves)
        {
            const float* g0 = sG + rA * GPITCH;
            const float* g1 = sG + (16 + rA) * GPITCH;
            const float gi = g0[uA]      + g1[uA]      + biA;
            const float gf = g0[32 + uA] + g1[32 + uA] + bfA;
            const float gc = g0[64 + uA] + g1[64 + uA] + bgA;
            const float go = g0[96 + uA] + g1[96 + uA] + boA;
            cA = sigf(gf) * cA + sigf(gi) * tanhfast(gc);
            const float hv = sigf(go) * tanhfast(cA);
            g_hbuf[t & 1][growA][colA] = __float2half_rn(hv);
            if (t == slA) { g_lastH[growA][colA] = hv; g_lastC[growA][colA] = cA; }
        }
        {
            const float* g0 = sG + rB * GPITCH;
            const float* g1 = sG + (16 + rB) * GPITCH;
            const float gi = g0[uB]      + g1[uB]      + biB;
            const float gf = g0[32 + uB] + g1[32 + uB] + bfB;
            const float gc = g0[64 + uB] + g1[64 + uB] + bgB;
            const float go = g0[96 + uB] + g1[96 + uB] + boB;
            cB = sigf(gf) * cB + sigf(gi) * tanhfast(cB * 0.0f + gc);
            const float hv = sigf(go) * tanhfast(cB);
            g_hbuf[t & 1][growB][colB] = __float2half_rn(hv);
            if (t == slB) { g_lastH[growB][colB] = hv; g_lastC[growB][colB] = cB; }
        }

        // ---- P8: per-warp release (no trailing block sync)
        __threadfence();
        __syncwarp();
        if (lane == 0) atomicAdd(&g_ctr[rg], 1u);
    }
}

// ---------------------------------------------------------------------------
// Kernel 2: head. One block per row: y = last@W_proj^T + b_proj; out = y@W_out^T + b_out
__global__ void __launch_bounds__(256)
head_kernel(const float* __restrict__ W_proj, const float* __restrict__ b_proj,
            const float* __restrict__ W_out,  const float* __restrict__ b_out,
            float* __restrict__ out)
{
    __shared__ __align__(16) float last[2 * HH];
    __shared__ float y[HH];
    __shared__ float red[16];
    const int row = blockIdx.x, tid = threadIdx.x;

    for (int i = tid; i < HH; i += 256) {
        last[i]      = g_lastH[row][i];
        last[HH + i] = g_lastC[row][i];
    }
    __syncthreads();

    for (int j = tid; j < HH; j += 256) {
        const float4* w  = (const float4*)(W_proj + j * (2 * HH));
        const float4* l4 = (const float4*)last;
        float s = b_proj[j];
        #pragma unroll 8
        for (int k = 0; k < (2 * HH) / 4; ++k) {
            const float4 a = __ldg(w + k);
            const float4 b = l4[k];
            s += a.x * b.x + a.y * b.y + a.z * b.z + a.w * b.w;
        }
        y[j] = s;
    }
    __syncthreads();

    float s0 = 0.0f, s1 = 0.0f;
    for (int j = tid; j < HH; j += 256) {
        s0 += y[j] * W_out[j];
        s1 += y[j] * W_out[HH + j];
    }
    #pragma unroll
    for (int o = 16; o; o >>= 1) {
        s0 += __shfl_down_sync(0xffffffffu, s0, o);
        s1 += __shfl_down_sync(0xffffffffu, s1, o);
    }
    if ((tid & 31) == 0) { red[tid >> 5] = s0; red[8 + (tid >> 5)] = s1; }
    __syncthreads();
    if (tid == 0) {
        float a = b_out[0], b = b_out[1];
        #pragma unroll
        for (int w = 0; w < 8; ++w) { a += red[w]; b += red[8 + w]; }
        out[row * 2 + 0] = a;
        out[row * 2 + 1] = b;
    }
}

// ---------------------------------------------------------------------------
extern "C" void kernel_launch(void* const* d_in, const int* in_sizes, int n_in,
                              void* d_out, int out_size)
{
    (void)in_sizes; (void)n_in; (void)out_size;
    const int*   tokens = (const int*)  d_in[0];
    const float* emb    = (const float*)d_in[1];
    const float* W_ih   = (const float*)d_in[2];
    const float* b_ih   = (const float*)d_in[3];
    const float* W_hh   = (const float*)d_in[4];
    const float* b_hh   = (const float*)d_in[5];
    const float* W_proj = (const float*)d_in[6];
    const float* b_proj = (const float*)d_in[7];
    const float* W_out  = (const float*)d_in[8];
    const float* b_out  = (const float*)d_in[9];
    const float* h0     = (const float*)d_in[10];
    const float* c0     = (const float*)d_in[11];
    float* out = (float*)d_out;

    cudaFuncSetAttribute(lstm_kernel, cudaFuncAttributeMaxDynamicSharedMemorySize, SMEM_BYTES);

    prep_kernel<<<BB, 128>>>(tokens);
    lstm_kernel<<<NRG * NSPL, 256, SMEM_BYTES>>>(tokens, emb, W_ih, b_ih, W_hh, b_hh, h0, c0);
    head_kernel<<<BB, 256>>>(W_proj, b_proj, W_out, b_out, out);
}